// round 15
// baseline (speedup 1.0000x reference)
#include <cuda_runtime.h>
#include <cuda_bf16.h>
#include <cstdint>

// Fixed shapes per reference: B=64, N=4096, K=128
#define KDIM 128
#define NROWS_MAX 262144
#define PRO_BLOCKS 1024

// Scratch (no device allocations -> __device__ globals).
// Overwrite semantics each call; ticket wraps via atomicInc -> replay-safe.
__device__ unsigned long long g_partial_lo[PRO_BLOCKS];
__device__ unsigned long long g_partial_hi[PRO_BLOCKS];
__device__ unsigned g_ticket;
__device__ int g_rank[KDIM];
__device__ float2 g_row[NROWS_MAX];     // per-row {u, 2*Phi(u)}

// ---------------------------------------------------------------------------
// f32x2 packed helpers (sm_103a FFMA2 path -- PTX only, ptxas won't auto-fuse)
// ---------------------------------------------------------------------------
__device__ __forceinline__ unsigned long long pk2(float lo, float hi) {
    unsigned long long r;
    asm("mov.b64 %0, {%1, %2};" : "=l"(r) : "f"(lo), "f"(hi));
    return r;
}
__device__ __forceinline__ void upk2(unsigned long long v, float& lo, float& hi) {
    asm("mov.b64 {%0, %1}, %2;" : "=f"(lo), "=f"(hi) : "l"(v));
}
__device__ __forceinline__ unsigned long long f2fma(unsigned long long a,
                                                    unsigned long long b,
                                                    unsigned long long c) {
    unsigned long long d;
    asm("fma.rn.f32x2 %0, %1, %2, %3;" : "=l"(d) : "l"(a), "l"(b), "l"(c));
    return d;
}
__device__ __forceinline__ unsigned long long f2mul(unsigned long long a,
                                                    unsigned long long b) {
    unsigned long long d;
    asm("mul.rn.f32x2 %0, %1, %2;" : "=l"(d) : "l"(a), "l"(b));
    return d;
}

// Compile-time packed constant (same float in both halves).
__device__ constexpr unsigned long long C2(float x) {
    unsigned u = __builtin_bit_cast(unsigned, x);
    return ((unsigned long long)u << 32) | u;
}

#define NLN2f (-0.69314718056f)

// ---------------------------------------------------------------------------
// Kernel 1: prologue. One THREAD per row:
//   - compute u = mu + sigma*eps[row], phi2 = 2*Phi(u); store float2 to g_row
//     (moves ~30 warp-inst of normcdff out of every k_main warp: 32x fewer
//     issues for the same math)
//   - accumulate 128-bit presence bitmap; block-reduce; last block (ticket)
//     combines 1024 partials and emits the rank LUT.
// ---------------------------------------------------------------------------
__global__ void __launch_bounds__(256)
k_prologue(const int* __restrict__ C, const float* __restrict__ eps,
           const float* __restrict__ mu, const float* __restrict__ sigma,
           int n_rows)
{
    unsigned long long lo = 0ull, hi = 0ull;
    const float mu_v = __ldg(mu);
    const float sg_v = __ldg(sigma);

    int stride = gridDim.x * blockDim.x;
    for (int r = blockIdx.x * blockDim.x + threadIdx.x; r < n_rows; r += stride) {
        int c = __ldg(C + r);
        if (c < 64) lo |= 1ull << c; else hi |= 1ull << (c & 63);
        float u    = fmaf(sg_v, __ldg(eps + r), mu_v);
        float phi2 = 2.0f * normcdff(u);
        g_row[r] = make_float2(u, phi2);
    }

    // Warp then block OR-reduce
    #pragma unroll
    for (int s = 16; s; s >>= 1) {
        lo |= __shfl_xor_sync(0xffffffffu, lo, s);
        hi |= __shfl_xor_sync(0xffffffffu, hi, s);
    }
    __shared__ unsigned long long slo[256], shi[256];
    __shared__ bool s_last;
    int wid = threadIdx.x >> 5;
    if ((threadIdx.x & 31) == 0) { slo[wid] = lo; shi[wid] = hi; }
    __syncthreads();

    if (threadIdx.x == 0) {
        unsigned long long blo = slo[0], bhi = shi[0];
        #pragma unroll
        for (int w = 1; w < 8; ++w) { blo |= slo[w]; bhi |= shi[w]; }
        g_partial_lo[blockIdx.x] = blo;
        g_partial_hi[blockIdx.x] = bhi;
        __threadfence();
        unsigned t = atomicInc(&g_ticket, PRO_BLOCKS - 1);   // wraps -> replay-safe
        s_last = (t == PRO_BLOCKS - 1);
    }
    __syncthreads();
    if (!s_last) return;

    // Last block: OR all 1024 partials (4 per thread, L1-bypass reads), emit rank.
    int t = threadIdx.x;
    unsigned long long alo = __ldcg(&g_partial_lo[t])       | __ldcg(&g_partial_lo[t + 256]);
    unsigned long long ahi = __ldcg(&g_partial_hi[t])       | __ldcg(&g_partial_hi[t + 256]);
    alo |= __ldcg(&g_partial_lo[t + 512]) | __ldcg(&g_partial_lo[t + 768]);
    ahi |= __ldcg(&g_partial_hi[t + 512]) | __ldcg(&g_partial_hi[t + 768]);
    slo[t] = alo; shi[t] = ahi;
    __syncthreads();
    for (int s = 128; s; s >>= 1) {
        if (t < s) { slo[t] |= slo[t + s]; shi[t] |= shi[t + s]; }
        __syncthreads();
    }
    if (t < KDIM) {
        unsigned long long flo = slo[0], fhi = shi[0];
        int r;
        if (t < 64) r = __popcll(flo & ((1ull << t) - 1ull));
        else        r = __popcll(flo) + __popcll(fhi & ((1ull << (t - 64)) - 1ull));
        g_rank[t] = r;                        // overwrite: replay-safe
    }
}

// ---------------------------------------------------------------------------
// Scalar tail of Giles' erfinv (w = -ln t >= 5): ~1.3% of elements.
// ---------------------------------------------------------------------------
__device__ __forceinline__ float tail_eval(float a, float l2) {
    float w = sqrtf(l2 * NLN2f) - 3.0f;
    float q = -0.000200214257f;
    q = fmaf(q, w, 0.000100950558f);
    q = fmaf(q, w, 0.00134934322f);
    q = fmaf(q, w, -0.00367342844f);
    q = fmaf(q, w, 0.00573950773f);
    q = fmaf(q, w, -0.0076224613f);
    q = fmaf(q, w, 0.00943887047f);
    q = fmaf(q, w, 1.00167406f);
    q = fmaf(q, w, 2.83297682f);
    return q * fmaf(1.41421356237f, a, -1.41421356237f);
}

// ---------------------------------------------------------------------------
// Packed central evaluation for a pair of uniforms. a = clip(U)*phi2 = 2p.
// ndtri(p) = sqrt2*erfinv(a-1); t = a*(2-a) = 1-(a-1)^2 (cancellation-safe).
// Central poly truncated to degree 6 (dropped c8,c7): relative error bound
// ~1.7e-4 (error carries the same xs factor as the result, so it stays
// relative-bounded even as z->0). Tail fixed up scalar.
// ---------------------------------------------------------------------------
__device__ __forceinline__ void pair_eval(float U0, float U1,
                                          unsigned long long phi2p,
                                          float& r0, float& r1)
{
    const float LO = 1e-7f;
    const float HI = 1.0f - 1e-7f;
    float c0 = fminf(fmaxf(U0, LO), HI);
    float c1 = fminf(fmaxf(U1, LO), HI);

    unsigned long long up = pk2(c0, c1);
    unsigned long long ap = f2mul(up, phi2p);                    // a = 2p
    unsigned long long tm = f2fma(ap, C2(-1.0f), C2(2.0f));      // 2 - a
    unsigned long long tp = f2mul(ap, tm);                       // t = a(2-a)

    float t0, t1;
    upk2(tp, t0, t1);
    float l20 = __log2f(t0);
    float l21 = __log2f(t1);

    unsigned long long w = f2fma(pk2(l20, l21), C2(NLN2f), C2(-2.5f)); // (-ln t)-2.5
    unsigned long long q = C2(-3.5233877e-06f);                  // degree-6 start
    q = f2fma(q, w, C2(-4.39150654e-06f));
    q = f2fma(q, w, C2(0.00021858087f));
    q = f2fma(q, w, C2(-0.00125372503f));
    q = f2fma(q, w, C2(-0.00417768164f));
    q = f2fma(q, w, C2(0.246640727f));
    q = f2fma(q, w, C2(1.50140941f));

    unsigned long long xs = f2fma(ap, C2(1.41421356237f), C2(-1.41421356237f));
    unsigned long long rp = f2mul(q, xs);
    upk2(rp, r0, r1);

    // Rare tail fixups (w >= 5  <=>  l2 <= -5/ln2)
    const float TAILT = -7.2134752f;
    if (l20 <= TAILT) { float a0, a1d; upk2(ap, a0, a1d); r0 = tail_eval(a0, l20); }
    if (l21 <= TAILT) { float a0d, a1; upk2(ap, a0d, a1); r1 = tail_eval(a1, l21); }
}

// ---------------------------------------------------------------------------
// Kernel 2: main. One warp per row (b,i), K=128 -> float4 per lane.
// Row scalars are precomputed: just 3 broadcast loads per warp.
// ---------------------------------------------------------------------------
__global__ void __launch_bounds__(256, 8)
k_main(const int*   __restrict__ C,
       const float* __restrict__ U,
       float*       __restrict__ out,
       int n_rows)
{
    int gwarp = (blockIdx.x * blockDim.x + threadIdx.x) >> 5;
    int lane  = threadIdx.x & 31;
    if (gwarp >= n_rows) return;

    const int row = gwarp;

    // Row scalars (same-address across warp -> broadcast; g_row is L2-hot).
    float2 up   = __ldg(&g_row[row]);
    float u     = up.x;
    int   cnew  = g_rank[__ldg(C + row)];
    unsigned long long phi2p = pk2(up.y, up.y);

    size_t base = (size_t)row * KDIM;
    float4 uv = __ldcs(reinterpret_cast<const float4*>(U + base) + lane);

    float4 z;
    pair_eval(uv.x, uv.y, phi2p, z.x, z.y);
    pair_eval(uv.z, uv.w, phi2p, z.z, z.w);

    // Patch: the single lane that owns column cnew substitutes u.
    if ((cnew >> 2) == lane) {
        int ci = cnew & 3;
        if (ci == 0) z.x = u;
        else if (ci == 1) z.y = u;
        else if (ci == 2) z.z = u;
        else z.w = u;
    }

    __stcs(reinterpret_cast<float4*>(out + base) + lane, z);
}

// ---------------------------------------------------------------------------
// Launch. Inputs per metadata order: C, eps, U, mu, sigma.
// ---------------------------------------------------------------------------
extern "C" void kernel_launch(void* const* d_in, const int* in_sizes, int n_in,
                              void* d_out, int out_size)
{
    const int*   C     = (const int*)  d_in[0];
    const float* eps   = (const float*)d_in[1];
    const float* U     = (const float*)d_in[2];
    const float* mu    = (const float*)d_in[3];
    const float* sigma = (const float*)d_in[4];
    float*       out   = (float*)d_out;

    const int n_rows = in_sizes[0];          // B*N = 262144

    k_prologue<<<PRO_BLOCKS, 256>>>(C, eps, mu, sigma, n_rows);

    // One warp per row, 8 warps per block (proven fastest shape).
    {
        int threads = 256;
        int wpb     = threads / 32;
        int blocks  = (n_rows + wpb - 1) / wpb;
        k_main<<<blocks, threads>>>(C, U, out, n_rows);
    }
}

// round 16
// speedup vs baseline: 1.3335x; 1.3335x over previous
#include <cuda_runtime.h>
#include <cuda_bf16.h>
#include <cstdint>

// Fixed shapes per reference: B=64, N=4096, K=128
#define KDIM 128
#define SCATTER_BLOCKS 256

// Scratch (no device allocations -> __device__ globals).
// Overwrite semantics; ticket wraps via atomicInc -> graph-replay-safe.
__device__ unsigned long long g_partial_lo[SCATTER_BLOCKS];
__device__ unsigned long long g_partial_hi[SCATTER_BLOCKS];
__device__ unsigned g_ticket;
__device__ int g_rank[KDIM];

// ---------------------------------------------------------------------------
// f32x2 packed helpers (sm_103a FFMA2 path -- PTX only, ptxas won't auto-fuse)
// ---------------------------------------------------------------------------
__device__ __forceinline__ unsigned long long pk2(float lo, float hi) {
    unsigned long long r;
    asm("mov.b64 %0, {%1, %2};" : "=l"(r) : "f"(lo), "f"(hi));
    return r;
}
__device__ __forceinline__ void upk2(unsigned long long v, float& lo, float& hi) {
    asm("mov.b64 {%0, %1}, %2;" : "=f"(lo), "=f"(hi) : "l"(v));
}
__device__ __forceinline__ unsigned long long f2fma(unsigned long long a,
                                                    unsigned long long b,
                                                    unsigned long long c) {
    unsigned long long d;
    asm("fma.rn.f32x2 %0, %1, %2, %3;" : "=l"(d) : "l"(a), "l"(b), "l"(c));
    return d;
}
__device__ __forceinline__ unsigned long long f2mul(unsigned long long a,
                                                    unsigned long long b) {
    unsigned long long d;
    asm("mul.rn.f32x2 %0, %1, %2;" : "=l"(d) : "l"(a), "l"(b));
    return d;
}

// Compile-time packed constant (same float in both halves).
__device__ constexpr unsigned long long C2(float x) {
    unsigned u = __builtin_bit_cast(unsigned, x);
    return ((unsigned long long)u << 32) | u;
}

#define NLN2f (-0.69314718056f)

// ---------------------------------------------------------------------------
// Kernel 1: presence bitmap + rank LUT in ONE kernel (threadfence reduction,
// last block combines). 256 blocks x 256 threads, one int4 load per thread.
// ---------------------------------------------------------------------------
__global__ void __launch_bounds__(256)
k_relabel(const int4* __restrict__ C4, int n4, const int* __restrict__ C, int n_rows)
{
    unsigned long long lo = 0ull, hi = 0ull;
    int i = blockIdx.x * blockDim.x + threadIdx.x;
    int stride = gridDim.x * blockDim.x;

    #define SETB(v) { if ((v) < 64) lo |= 1ull << (v); else hi |= 1ull << ((v) & 63); }
    for (; i < n4; i += stride) {                 // 1 iteration for the real shape
        int4 a = __ldg(C4 + i);
        SETB(a.x) SETB(a.y) SETB(a.z) SETB(a.w)
    }
    if (blockIdx.x == 0 && threadIdx.x < (n_rows & 3)) {   // int4 tail (none here)
        int v = __ldg(C + n4 * 4 + threadIdx.x);
        SETB(v)
    }
    #undef SETB

    #pragma unroll
    for (int s = 16; s; s >>= 1) {
        lo |= __shfl_xor_sync(0xffffffffu, lo, s);
        hi |= __shfl_xor_sync(0xffffffffu, hi, s);
    }
    __shared__ unsigned long long slo[256], shi[256];
    __shared__ bool s_last;
    int wid = threadIdx.x >> 5;
    if ((threadIdx.x & 31) == 0) { slo[wid] = lo; shi[wid] = hi; }
    __syncthreads();

    if (threadIdx.x == 0) {
        unsigned long long blo = slo[0], bhi = shi[0];
        #pragma unroll
        for (int w = 1; w < 8; ++w) { blo |= slo[w]; bhi |= shi[w]; }
        g_partial_lo[blockIdx.x] = blo;
        g_partial_hi[blockIdx.x] = bhi;
        __threadfence();
        unsigned t = atomicInc(&g_ticket, SCATTER_BLOCKS - 1);  // wraps -> replay-safe
        s_last = (t == SCATTER_BLOCKS - 1);
    }
    __syncthreads();
    if (!s_last) return;

    int t = threadIdx.x;
    slo[t] = __ldcg(&g_partial_lo[t]);
    shi[t] = __ldcg(&g_partial_hi[t]);
    __syncthreads();
    for (int s = 128; s; s >>= 1) {
        if (t < s) { slo[t] |= slo[t + s]; shi[t] |= shi[t + s]; }
        __syncthreads();
    }
    if (t < KDIM) {
        unsigned long long flo = slo[0], fhi = shi[0];
        int r;
        if (t < 64) r = __popcll(flo & ((1ull << t) - 1ull));
        else        r = __popcll(flo) + __popcll(fhi & ((1ull << (t - 64)) - 1ull));
        g_rank[t] = r;                        // overwrite: replay-safe
    }
}

// ---------------------------------------------------------------------------
// Cheap row scalar: phi2(u) = 2*Phi(u) = erfc(-u/sqrt2), Numerical-Recipes
// erfc approximation (rel err <= 1.2e-7): rcp.approx + 9 FMA + __expf.
// ~16 inst vs ~40 for normcdff. Computed once per warp (uniform).
// ---------------------------------------------------------------------------
__device__ __forceinline__ float phi2_of(float u) {
    float x  = -0.70710678118f * u;
    float ax = fabsf(x);
    float d  = fmaf(0.5f, ax, 1.0f);
    float t;  asm("rcp.approx.f32 %0, %1;" : "=f"(t) : "f"(d));
    float p = 0.17087277f;
    p = fmaf(p, t, -0.82215223f);
    p = fmaf(p, t, 1.48851587f);
    p = fmaf(p, t, -1.13520398f);
    p = fmaf(p, t, 0.27886807f);
    p = fmaf(p, t, -0.18628806f);
    p = fmaf(p, t, 0.09678418f);
    p = fmaf(p, t, 0.37409196f);
    p = fmaf(p, t, 1.00002368f);
    p = fmaf(p, t, -1.26551223f);
    float e = t * __expf(fmaf(-ax, ax, p));
    return (x >= 0.0f) ? e : (2.0f - e);
}

// ---------------------------------------------------------------------------
// Scalar tail of Giles' erfinv (w = -ln t >= 5): ~1.3% of elements.
// ---------------------------------------------------------------------------
__device__ __forceinline__ float tail_eval(float a, float l2) {
    float w = sqrtf(l2 * NLN2f) - 3.0f;
    float q = -0.000200214257f;
    q = fmaf(q, w, 0.000100950558f);
    q = fmaf(q, w, 0.00134934322f);
    q = fmaf(q, w, -0.00367342844f);
    q = fmaf(q, w, 0.00573950773f);
    q = fmaf(q, w, -0.0076224613f);
    q = fmaf(q, w, 0.00943887047f);
    q = fmaf(q, w, 1.00167406f);
    q = fmaf(q, w, 2.83297682f);
    return q * fmaf(1.41421356237f, a, -1.41421356237f);
}

// ---------------------------------------------------------------------------
// Packed central evaluation for a pair of uniforms. a = clip(U)*phi2 = 2p.
// ndtri(p) = sqrt2*erfinv(a-1); t = a*(2-a) = 1-(a-1)^2 (cancellation-safe).
// Central poly degree-6 (validated R15: rel err ~3e-5 vs 1e-3 budget).
// ---------------------------------------------------------------------------
__device__ __forceinline__ void pair_eval(float U0, float U1,
                                          unsigned long long phi2p,
                                          float& r0, float& r1)
{
    const float LO = 1e-7f;
    const float HI = 1.0f - 1e-7f;
    float c0 = fminf(fmaxf(U0, LO), HI);
    float c1 = fminf(fmaxf(U1, LO), HI);

    unsigned long long up = pk2(c0, c1);
    unsigned long long ap = f2mul(up, phi2p);                    // a = 2p
    unsigned long long tm = f2fma(ap, C2(-1.0f), C2(2.0f));      // 2 - a
    unsigned long long tp = f2mul(ap, tm);                       // t = a(2-a)

    float t0, t1;
    upk2(tp, t0, t1);
    float l20 = __log2f(t0);
    float l21 = __log2f(t1);

    unsigned long long w = f2fma(pk2(l20, l21), C2(NLN2f), C2(-2.5f)); // (-ln t)-2.5
    unsigned long long q = C2(-3.5233877e-06f);                  // degree-6 head
    q = f2fma(q, w, C2(-4.39150654e-06f));
    q = f2fma(q, w, C2(0.00021858087f));
    q = f2fma(q, w, C2(-0.00125372503f));
    q = f2fma(q, w, C2(-0.00417768164f));
    q = f2fma(q, w, C2(0.246640727f));
    q = f2fma(q, w, C2(1.50140941f));

    unsigned long long xs = f2fma(ap, C2(1.41421356237f), C2(-1.41421356237f));
    unsigned long long rp = f2mul(q, xs);
    upk2(rp, r0, r1);

    // Rare tail fixups (w >= 5  <=>  l2 <= -5/ln2)
    const float TAILT = -7.2134752f;
    if (l20 <= TAILT) { float a0, a1d; upk2(ap, a0, a1d); r0 = tail_eval(a0, l20); }
    if (l21 <= TAILT) { float a0d, a1; upk2(ap, a0d, a1); r1 = tail_eval(a1, l21); }
}

// ---------------------------------------------------------------------------
// Kernel 2: main. One warp per row (b,i), K=128 -> float4 per lane.
// Row scalars computed IN-WARP (R15 showed offloading them serializes a
// dependent L2 load on the critical path and regresses).
// ---------------------------------------------------------------------------
__global__ void __launch_bounds__(256, 8)
k_main(const int*   __restrict__ C,
       const float* __restrict__ eps,
       const float* __restrict__ U,
       const float* __restrict__ mu,
       const float* __restrict__ sigma,
       float*       __restrict__ out,
       int n_rows)
{
    int gwarp = (blockIdx.x * blockDim.x + threadIdx.x) >> 5;
    int lane  = threadIdx.x & 31;
    if (gwarp >= n_rows) return;

    const int row = gwarp;

    // Row scalars (same-address across warp -> broadcast loads).
    float mu_v = __ldg(mu);
    float sg_v = __ldg(sigma);
    float u    = fmaf(sg_v, __ldg(eps + row), mu_v);
    int   cnew = g_rank[__ldg(C + row)];
    float phi2 = phi2_of(u);
    unsigned long long phi2p = pk2(phi2, phi2);

    size_t base = (size_t)row * KDIM;
    float4 uv = __ldcs(reinterpret_cast<const float4*>(U + base) + lane);

    float4 z;
    pair_eval(uv.x, uv.y, phi2p, z.x, z.y);
    pair_eval(uv.z, uv.w, phi2p, z.z, z.w);

    // Patch: the single lane that owns column cnew substitutes u.
    if ((cnew >> 2) == lane) {
        int ci = cnew & 3;
        if (ci == 0) z.x = u;
        else if (ci == 1) z.y = u;
        else if (ci == 2) z.z = u;
        else z.w = u;
    }

    __stcs(reinterpret_cast<float4*>(out + base) + lane, z);
}

// ---------------------------------------------------------------------------
// Launch. Inputs per metadata order: C, eps, U, mu, sigma.
// ---------------------------------------------------------------------------
extern "C" void kernel_launch(void* const* d_in, const int* in_sizes, int n_in,
                              void* d_out, int out_size)
{
    const int*   C     = (const int*)  d_in[0];
    const float* eps   = (const float*)d_in[1];
    const float* U     = (const float*)d_in[2];
    const float* mu    = (const float*)d_in[3];
    const float* sigma = (const float*)d_in[4];
    float*       out   = (float*)d_out;

    const int n_rows = in_sizes[0];          // B*N = 262144
    const int n4     = n_rows >> 2;

    k_relabel<<<SCATTER_BLOCKS, 256>>>((const int4*)C, n4, C, n_rows);

    // One warp per row, 8 warps per block (proven fastest shape).
    {
        int threads = 256;
        int wpb     = threads / 32;
        int blocks  = (n_rows + wpb - 1) / wpb;
        k_main<<<blocks, threads>>>(C, eps, U, mu, sigma, out, n_rows);
    }
}